// round 4
// baseline (speedup 1.0000x reference)
#include <cuda_runtime.h>
#include <math_constants.h>

#define N_NODES 8192
#define F 512
#define ALPHA 0.2f
#define NPART 128          // stage-1 partial blocks (4 o-rows each)

// Scratch (no dynamic allocation allowed)
__device__ __align__(16) float g_part1[NPART * F];
__device__ __align__(16) float g_part2[NPART * F];
__device__ __align__(16) float g_w1[F];
__device__ __align__(16) float g_w2[F];
__device__ __align__(16) float g_s1[N_NODES];
__device__ __align__(16) float g_s2[N_NODES];

// ---------------------------------------------------------------------------
// Stage 1: partial fold of attention vector through W.
// CTA b handles o in [4b, 4b+4). Thread t covers k = t and k = t+256.
// ---------------------------------------------------------------------------
__global__ void wvec_part_kernel(const float* __restrict__ W,
                                 const float* __restrict__ a) {
    const int b = blockIdx.x;
    const int t = threadIdx.x;            // 0..255
    const int o0 = b * 4;
    float acc1a = 0.f, acc2a = 0.f;       // for k = t
    float acc1b = 0.f, acc2b = 0.f;       // for k = t + 256
    #pragma unroll
    for (int j = 0; j < 4; j++) {
        const int o = o0 + j;
        const float a1 = a[o];
        const float a2 = a[F + o];
        const float wa = W[o * F + t];
        const float wb = W[o * F + t + 256];
        acc1a = fmaf(wa, a1, acc1a);
        acc2a = fmaf(wa, a2, acc2a);
        acc1b = fmaf(wb, a1, acc1b);
        acc2b = fmaf(wb, a2, acc2b);
    }
    g_part1[b * F + t]       = acc1a;
    g_part1[b * F + t + 256] = acc1b;
    g_part2[b * F + t]       = acc2a;
    g_part2[b * F + t + 256] = acc2b;
}

// ---------------------------------------------------------------------------
// Stage 2: reduce NPART partials per k. 2 CTAs x 256 threads = 512 threads.
// ---------------------------------------------------------------------------
__global__ void wvec_reduce_kernel() {
    const int k = blockIdx.x * 256 + threadIdx.x;   // 0..511
    float s1 = 0.f, s2 = 0.f;
    #pragma unroll 16
    for (int b = 0; b < NPART; b++) {
        s1 += g_part1[b * F + k];
        s2 += g_part2[b * F + k];
    }
    g_w1[k] = s1;
    g_w2[k] = s2;
}

// ---------------------------------------------------------------------------
// Per-node scores. One warp per node row.
// ---------------------------------------------------------------------------
__global__ void sdot_kernel(const float* __restrict__ nodes) {
    int warp = (blockIdx.x * blockDim.x + threadIdx.x) >> 5;
    int lane = threadIdx.x & 31;
    if (warp >= N_NODES) return;
    const float4* nrow = (const float4*)(nodes + (size_t)warp * F);
    const float4* w1v  = (const float4*)g_w1;
    const float4* w2v  = (const float4*)g_w2;
    float a1 = 0.f, a2 = 0.f;
    #pragma unroll
    for (int i = 0; i < (F / 4) / 32; i++) {   // 4 iters
        int idx = lane + i * 32;
        float4 v = nrow[idx];
        float4 x = w1v[idx];
        float4 y = w2v[idx];
        a1 += v.x * x.x + v.y * x.y + v.z * x.z + v.w * x.w;
        a2 += v.x * y.x + v.y * y.y + v.z * y.z + v.w * y.w;
    }
    #pragma unroll
    for (int off = 16; off; off >>= 1) {
        a1 += __shfl_xor_sync(0xffffffffu, a1, off);
        a2 += __shfl_xor_sync(0xffffffffu, a2, off);
    }
    if (lane == 0) {
        g_s1[warp] = a1;
        g_s2[warp] = a2;
    }
}

// ---------------------------------------------------------------------------
// Masked row softmax. One CTA per row; 1024 threads x 8 cols each.
// adj row read ONCE (evict-streaming); scores live in registers.
// 2 CTAs/SM = 2048 threads = 100% occupancy; barrier shadows overlapped.
// ---------------------------------------------------------------------------
__global__ void __launch_bounds__(1024, 2)
attn_kernel(const float* __restrict__ adj, float* __restrict__ out) {
    const int row = blockIdx.x;
    const float4* __restrict__ arow = (const float4*)(adj + (size_t)row * N_NODES);
    float4* __restrict__ orow = (float4*)(out + (size_t)row * N_NODES);
    const float4* __restrict__ s2v = (const float4*)g_s2;

    const float s1 = g_s1[row];
    const int tid  = threadIdx.x;
    const int lane = tid & 31;
    const int wid  = tid >> 5;           // 0..31

    float e[8];
    float lmax = -CUDART_INF_F;

    // Phase 1: stream adj (no L2 retention), masked leaky-relu, track max.
    #pragma unroll
    for (int c = 0; c < 2; c++) {
        int idx = c * 1024 + tid;         // float4 index within row
        float4 a4 = __ldcs(arow + idx);   // streaming: don't thrash L2
        float4 s4 = s2v[idx];             // hot, keep cached
        float x0 = s1 + s4.x; x0 = (x0 >= 0.f) ? x0 : ALPHA * x0;
        float x1 = s1 + s4.y; x1 = (x1 >= 0.f) ? x1 : ALPHA * x1;
        float x2 = s1 + s4.z; x2 = (x2 >= 0.f) ? x2 : ALPHA * x2;
        float x3 = s1 + s4.w; x3 = (x3 >= 0.f) ? x3 : ALPHA * x3;
        x0 = (a4.x >= 0.5f) ? x0 : -CUDART_INF_F;
        x1 = (a4.y >= 0.5f) ? x1 : -CUDART_INF_F;
        x2 = (a4.z >= 0.5f) ? x2 : -CUDART_INF_F;
        x3 = (a4.w >= 0.5f) ? x3 : -CUDART_INF_F;
        e[c * 4 + 0] = x0;
        e[c * 4 + 1] = x1;
        e[c * 4 + 2] = x2;
        e[c * 4 + 3] = x3;
        lmax = fmaxf(lmax, fmaxf(fmaxf(x0, x1), fmaxf(x2, x3)));
    }

    // Block-reduce max (32 warps)
    __shared__ float sm_max[32];
    __shared__ float sm_sum[32];
    #pragma unroll
    for (int off = 16; off; off >>= 1)
        lmax = fmaxf(lmax, __shfl_xor_sync(0xffffffffu, lmax, off));
    if (lane == 0) sm_max[wid] = lmax;
    __syncthreads();
    float rmax = sm_max[0];
    #pragma unroll
    for (int w = 1; w < 32; w++) rmax = fmaxf(rmax, sm_max[w]);

    // Phase 2: exponentiate (in registers), accumulate sum.
    float lsum = 0.f;
    #pragma unroll
    for (int i = 0; i < 8; i++) {
        float p = __expf(e[i] - rmax);    // exp(-inf) -> 0 for masked entries
        e[i] = p;
        lsum += p;
    }
    #pragma unroll
    for (int off = 16; off; off >>= 1)
        lsum += __shfl_xor_sync(0xffffffffu, lsum, off);
    if (lane == 0) sm_sum[wid] = lsum;
    __syncthreads();
    float rsum = sm_sum[0];
    #pragma unroll
    for (int w = 1; w < 32; w++) rsum += sm_sum[w];
    float inv = 1.f / rsum;

    // Phase 3: normalize + streaming write.
    #pragma unroll
    for (int c = 0; c < 2; c++) {
        int idx = c * 1024 + tid;
        float4 o4;
        o4.x = e[c * 4 + 0] * inv;
        o4.y = e[c * 4 + 1] * inv;
        o4.z = e[c * 4 + 2] * inv;
        o4.w = e[c * 4 + 3] * inv;
        __stcs(orow + idx, o4);
    }
}

// ---------------------------------------------------------------------------
extern "C" void kernel_launch(void* const* d_in, const int* in_sizes, int n_in,
                              void* d_out, int out_size) {
    const float* nodes = (const float*)d_in[0];   // [8192, 512]
    const float* adj   = (const float*)d_in[1];   // [8192, 8192]
    const float* W     = (const float*)d_in[2];   // [512, 512]
    const float* a     = (const float*)d_in[3];   // [1024]
    float* out = (float*)d_out;                   // [8192, 8192]

    wvec_part_kernel<<<NPART, 256>>>(W, a);
    wvec_reduce_kernel<<<2, 256>>>();
    sdot_kernel<<<N_NODES / 8, 256>>>(nodes);     // 8 warps/block, 1 warp/row
    attn_kernel<<<N_NODES, 1024>>>(adj, out);
}

// round 6
// speedup vs baseline: 1.1982x; 1.1982x over previous
#include <cuda_runtime.h>
#include <math_constants.h>

#define N_NODES 8192
#define F 512
#define ALPHA 0.2f
#define NPART 128          // stage-1 partial blocks (4 o-rows each)

// Scratch (no dynamic allocation allowed)
__device__ __align__(16) float g_part1[NPART * F];
__device__ __align__(16) float g_part2[NPART * F];
__device__ __align__(16) float g_w1[F];
__device__ __align__(16) float g_w2[F];
__device__ __align__(16) float g_s1[N_NODES];
__device__ __align__(16) float g_s2[N_NODES];

// ---------------------------------------------------------------------------
// Stage 1: partial fold of attention vector through W.
// CTA b handles o in [4b, 4b+4). Thread t covers k = t and k = t+256.
// ---------------------------------------------------------------------------
__global__ void wvec_part_kernel(const float* __restrict__ W,
                                 const float* __restrict__ a) {
    const int b = blockIdx.x;
    const int t = threadIdx.x;            // 0..255
    const int o0 = b * 4;
    float acc1a = 0.f, acc2a = 0.f;       // for k = t
    float acc1b = 0.f, acc2b = 0.f;       // for k = t + 256
    #pragma unroll
    for (int j = 0; j < 4; j++) {
        const int o = o0 + j;
        const float a1 = a[o];
        const float a2 = a[F + o];
        const float wa = W[o * F + t];
        const float wb = W[o * F + t + 256];
        acc1a = fmaf(wa, a1, acc1a);
        acc2a = fmaf(wa, a2, acc2a);
        acc1b = fmaf(wb, a1, acc1b);
        acc2b = fmaf(wb, a2, acc2b);
    }
    g_part1[b * F + t]       = acc1a;
    g_part1[b * F + t + 256] = acc1b;
    g_part2[b * F + t]       = acc2a;
    g_part2[b * F + t + 256] = acc2b;
}

// ---------------------------------------------------------------------------
// Stage 2: reduce NPART partials per k. 2 CTAs x 256 threads = 512 threads.
// ---------------------------------------------------------------------------
__global__ void wvec_reduce_kernel() {
    const int k = blockIdx.x * 256 + threadIdx.x;   // 0..511
    float s1 = 0.f, s2 = 0.f;
    #pragma unroll 16
    for (int b = 0; b < NPART; b++) {
        s1 += g_part1[b * F + k];
        s2 += g_part2[b * F + k];
    }
    g_w1[k] = s1;
    g_w2[k] = s2;
}

// ---------------------------------------------------------------------------
// Per-node scores. One warp per node row.
// ---------------------------------------------------------------------------
__global__ void sdot_kernel(const float* __restrict__ nodes) {
    int warp = (blockIdx.x * blockDim.x + threadIdx.x) >> 5;
    int lane = threadIdx.x & 31;
    if (warp >= N_NODES) return;
    const float4* nrow = (const float4*)(nodes + (size_t)warp * F);
    const float4* w1v  = (const float4*)g_w1;
    const float4* w2v  = (const float4*)g_w2;
    float a1 = 0.f, a2 = 0.f;
    #pragma unroll
    for (int i = 0; i < (F / 4) / 32; i++) {   // 4 iters
        int idx = lane + i * 32;
        float4 v = nrow[idx];
        float4 x = w1v[idx];
        float4 y = w2v[idx];
        a1 += v.x * x.x + v.y * x.y + v.z * x.z + v.w * x.w;
        a2 += v.x * y.x + v.y * y.y + v.z * y.z + v.w * y.w;
    }
    #pragma unroll
    for (int off = 16; off; off >>= 1) {
        a1 += __shfl_xor_sync(0xffffffffu, a1, off);
        a2 += __shfl_xor_sync(0xffffffffu, a2, off);
    }
    if (lane == 0) {
        g_s1[warp] = a1;
        g_s2[warp] = a2;
    }
}

// ---------------------------------------------------------------------------
// Masked row softmax. One CTA per row; 256 threads x 32 cols each.
// adj row read ONCE; 8 independent float4 loads in flight per thread (deep
// MLP hides DRAM latency); barriers span only 8 warps. Empirically the best
// thread-granularity (R1 ~84us vs R3 89.9 vs R4 103.6 for wider CTAs).
// ---------------------------------------------------------------------------
__global__ void __launch_bounds__(256, 4)
attn_kernel(const float* __restrict__ adj, float* __restrict__ out) {
    const int row = blockIdx.x;
    const float4* __restrict__ arow = (const float4*)(adj + (size_t)row * N_NODES);
    float4* __restrict__ orow = (float4*)(out + (size_t)row * N_NODES);
    const float4* __restrict__ s2v = (const float4*)g_s2;

    const float s1 = g_s1[row];
    const int tid  = threadIdx.x;
    const int lane = tid & 31;
    const int wid  = tid >> 5;

    float e[32];
    float lmax = -CUDART_INF_F;

    // Phase 1: load adj, compute masked leaky-relu scores, track row max.
    #pragma unroll
    for (int c = 0; c < 8; c++) {
        int idx = c * 256 + tid;          // float4 index within row
        float4 a4 = arow[idx];
        float4 s4 = s2v[idx];
        float x0 = s1 + s4.x; x0 = (x0 >= 0.f) ? x0 : ALPHA * x0;
        float x1 = s1 + s4.y; x1 = (x1 >= 0.f) ? x1 : ALPHA * x1;
        float x2 = s1 + s4.z; x2 = (x2 >= 0.f) ? x2 : ALPHA * x2;
        float x3 = s1 + s4.w; x3 = (x3 >= 0.f) ? x3 : ALPHA * x3;
        x0 = (a4.x >= 0.5f) ? x0 : -CUDART_INF_F;
        x1 = (a4.y >= 0.5f) ? x1 : -CUDART_INF_F;
        x2 = (a4.z >= 0.5f) ? x2 : -CUDART_INF_F;
        x3 = (a4.w >= 0.5f) ? x3 : -CUDART_INF_F;
        e[c * 4 + 0] = x0;
        e[c * 4 + 1] = x1;
        e[c * 4 + 2] = x2;
        e[c * 4 + 3] = x3;
        lmax = fmaxf(lmax, fmaxf(fmaxf(x0, x1), fmaxf(x2, x3)));
    }

    // Block-reduce max (8 warps)
    __shared__ float sm_max[8];
    __shared__ float sm_sum[8];
    #pragma unroll
    for (int off = 16; off; off >>= 1)
        lmax = fmaxf(lmax, __shfl_xor_sync(0xffffffffu, lmax, off));
    if (lane == 0) sm_max[wid] = lmax;
    __syncthreads();
    float rmax = sm_max[0];
    #pragma unroll
    for (int w = 1; w < 8; w++) rmax = fmaxf(rmax, sm_max[w]);

    // Phase 2: exponentiate (in registers), accumulate sum.
    float lsum = 0.f;
    #pragma unroll
    for (int i = 0; i < 32; i++) {
        float p = __expf(e[i] - rmax);   // exp(-inf) -> 0 for masked entries
        e[i] = p;
        lsum += p;
    }
    #pragma unroll
    for (int off = 16; off; off >>= 1)
        lsum += __shfl_xor_sync(0xffffffffu, lsum, off);
    if (lane == 0) sm_sum[wid] = lsum;
    __syncthreads();
    float rsum = sm_sum[0];
    #pragma unroll
    for (int w = 1; w < 8; w++) rsum += sm_sum[w];
    float inv = 1.f / rsum;

    // Phase 3: normalize + write.
    #pragma unroll
    for (int c = 0; c < 8; c++) {
        int idx = c * 256 + tid;
        float4 o4;
        o4.x = e[c * 4 + 0] * inv;
        o4.y = e[c * 4 + 1] * inv;
        o4.z = e[c * 4 + 2] * inv;
        o4.w = e[c * 4 + 3] * inv;
        orow[idx] = o4;
    }
}

// ---------------------------------------------------------------------------
extern "C" void kernel_launch(void* const* d_in, const int* in_sizes, int n_in,
                              void* d_out, int out_size) {
    const float* nodes = (const float*)d_in[0];   // [8192, 512]
    const float* adj   = (const float*)d_in[1];   // [8192, 8192]
    const float* W     = (const float*)d_in[2];   // [512, 512]
    const float* a     = (const float*)d_in[3];   // [1024]
    float* out = (float*)d_out;                   // [8192, 8192]

    wvec_part_kernel<<<NPART, 256>>>(W, a);
    wvec_reduce_kernel<<<2, 256>>>();
    sdot_kernel<<<N_NODES / 8, 256>>>(nodes);     // 8 warps/block, 1 warp/row
    attn_kernel<<<N_NODES, 256>>>(adj, out);
}